// round 7
// baseline (speedup 1.0000x reference)
#include <cuda_runtime.h>
#include <cuda_bf16.h>
#include <math.h>
#include <stdint.h>

#define B_  2
#define S_  512
#define V_  32000
#define D_  768
#define F_  2048
#define L_  4
#define H_  12
#define HD_ 64
#define FCS_ 8
#define YW_ (S_ + FCS_ - 1)   /* 519 */
#define NT_ (B_ * S_)         /* 1024 rows */

// ---------------- static scratch (allocation-free rule) ----------------
__device__ float  g_h [NT_ * D_];
__device__ float  g_a [NT_ * D_];
__device__ float  g_q [NT_ * D_];
__device__ float  g_k [NT_ * D_];
__device__ float  g_v [NT_ * D_];
__device__ float  g_o [NT_ * D_];
__device__ float  g_g1[NT_ * F_];
__device__ float  g_u1[NT_ * F_];
__device__ float  g_c [NT_ * V_];      // context head logits c (131 MB)
__device__ float2 g_rope[S_ * 32];
__device__ double g_acc[4];            // [0]=softplus_sum [1]=delta [2]=nll_sum [3]=valid

__device__ __forceinline__ float softplusf(float x) {
    if (x > 15.0f) return x;
    return log1pf(expf(x));
}

__device__ __forceinline__ uint32_t f2tf32(float x) {
    uint32_t r; asm("cvt.rna.tf32.f32 %0, %1;" : "=r"(r) : "f"(x)); return r;
}

__device__ __forceinline__ void mma_tf32(float& c0, float& c1, float& c2, float& c3,
                                         uint32_t a0, uint32_t a1, uint32_t a2, uint32_t a3,
                                         uint32_t b0, uint32_t b1) {
    asm volatile("mma.sync.aligned.m16n8k8.row.col.f32.tf32.tf32.f32 "
                 "{%0,%1,%2,%3}, {%4,%5,%6,%7}, {%8,%9}, {%0,%1,%2,%3};"
                 : "+f"(c0), "+f"(c1), "+f"(c2), "+f"(c3)
                 : "r"(a0), "r"(a1), "r"(a2), "r"(a3), "r"(b0), "r"(b1));
}

__device__ __forceinline__ void mma_bf16(float& c0, float& c1, float& c2, float& c3,
                                         uint32_t a0, uint32_t a1, uint32_t a2, uint32_t a3,
                                         uint32_t b0, uint32_t b1) {
    asm volatile("mma.sync.aligned.m16n8k16.row.col.f32.bf16.bf16.f32 "
                 "{%0,%1,%2,%3}, {%4,%5,%6,%7}, {%8,%9}, {%0,%1,%2,%3};"
                 : "+f"(c0), "+f"(c1), "+f"(c2), "+f"(c3)
                 : "r"(a0), "r"(a1), "r"(a2), "r"(a3), "r"(b0), "r"(b1));
}

__device__ __forceinline__ uint32_t pkbf2(float a, float b) {
    __nv_bfloat162 t = __floats2bfloat162_rn(a, b);
    return *(uint32_t*)&t;
}
__device__ __forceinline__ float bfhi(float a) {
    return __bfloat162float(__float2bfloat16_rn(a));
}

__global__ void zero_acc_kernel() {
    if (threadIdx.x < 4) g_acc[threadIdx.x] = 0.0;
}

// ---------------- embedding gather ----------------
__global__ void embed_kernel(const int* __restrict__ x, const float* __restrict__ emb) {
    int i = blockIdx.x * blockDim.x + threadIdx.x;
    if (i >= NT_ * D_) return;
    int row = i / D_;
    int d   = i - row * D_;
    g_h[i] = emb[(size_t)x[row] * D_ + d];
}

// ---------------- rmsnorm ----------------
__global__ void rmsnorm_kernel(const float* __restrict__ in, const float* __restrict__ w,
                               float* __restrict__ out) {
    int row = blockIdx.x;
    const float* ip = in + row * D_;
    float* op = out + row * D_;
    __shared__ float red[256];
    float ss = 0.f;
    for (int d = threadIdx.x; d < D_; d += 256) { float v = ip[d]; ss += v * v; }
    red[threadIdx.x] = ss; __syncthreads();
    for (int st = 128; st > 0; st >>= 1) {
        if (threadIdx.x < st) red[threadIdx.x] += red[threadIdx.x + st];
        __syncthreads();
    }
    float rs = rsqrtf(red[0] / (float)D_ + 1e-5f);
    for (int d = threadIdx.x; d < D_; d += 256) op[d] = ip[d] * rs * w[d];
}

#define TLD 20   /* smem row stride (u32): fragment loads conflict-free */

// =======================================================================
//  tf32 tensor-core NT-GEMM (head projections; validated, unchanged)
//  EPI: 0=store 4=store+softplus-sum
// =======================================================================
template<int BM, int BN, int WM, int WN, int EPI>
__device__ __forceinline__ void gemm_tc_core(const float* __restrict__ A,
                                             const float* __restrict__ Bw,
                                             float* __restrict__ C,
                                             const float* __restrict__ G,
                                             int N, int K,
                                             int bm, int bn) {
    constexpr int THREADS = WM * WN * 32;
    constexpr int WTM = BM / WM;
    constexpr int WTN = BN / WN;
    constexpr int MT  = WTM / 16;
    constexpr int NTT = WTN / 8;
    constexpr int RPP = THREADS / 2;
    constexpr int NLA = BM / RPP;
    constexpr int NLB = BN / RPP;

    __shared__ uint32_t As[2][BM][TLD];
    __shared__ uint32_t Bs[2][BN][TLD];
    __shared__ float sred[THREADS];

    const int tid  = threadIdx.x;
    const int lane = tid & 31;
    const int wid  = tid >> 5;
    const int wm   = wid / WN;
    const int wn   = wid % WN;

    const int lr = tid >> 1;
    const int ks = (tid & 1) * 8;
    const float* Ag = A  + (size_t)(bm + lr) * K + ks;
    const float* Bg = Bw + (size_t)(bn + lr) * K + ks;

    float acc[MT][NTT][4];
#pragma unroll
    for (int i = 0; i < MT; i++)
#pragma unroll
        for (int j = 0; j < NTT; j++)
#pragma unroll
            for (int q = 0; q < 4; q++) acc[i][j][q] = 0.f;

    float4 pa[NLA][2], pb[NLB][2];

#pragma unroll
    for (int l = 0; l < NLA; l++) {
        pa[l][0] = *(const float4*)(Ag + (size_t)l * RPP * K);
        pa[l][1] = *(const float4*)(Ag + (size_t)l * RPP * K + 4);
    }
#pragma unroll
    for (int l = 0; l < NLB; l++) {
        pb[l][0] = *(const float4*)(Bg + (size_t)l * RPP * K);
        pb[l][1] = *(const float4*)(Bg + (size_t)l * RPP * K + 4);
    }

    auto store_tiles = [&](int buf) {
#pragma unroll
        for (int l = 0; l < NLA; l++) {
            uint4 u0 = make_uint4(f2tf32(pa[l][0].x), f2tf32(pa[l][0].y),
                                  f2tf32(pa[l][0].z), f2tf32(pa[l][0].w));
            uint4 u1 = make_uint4(f2tf32(pa[l][1].x), f2tf32(pa[l][1].y),
                                  f2tf32(pa[l][1].z), f2tf32(pa[l][1].w));
            *(uint4*)&As[buf][lr + l * RPP][ks]     = u0;
            *(uint4*)&As[buf][lr + l * RPP][ks + 4] = u1;
        }
#pragma unroll
        for (int l = 0; l < NLB; l++) {
            uint4 u0 = make_uint4(f2tf32(pb[l][0].x), f2tf32(pb[l][0].y),
                                  f2tf32(pb[l][0].z), f2tf32(pb[l][0].w));
            uint4 u1 = make_uint4(f2tf32(pb[l][1].x), f2tf32(pb[l][1].y),
                                  f2tf32(pb[l][1].z), f2tf32(pb[l][1].w));
            *(uint4*)&Bs[buf][lr + l * RPP][ks]     = u0;
            *(uint4*)&Bs[buf][lr + l * RPP][ks + 4] = u1;
        }
    };

    store_tiles(0);
    __syncthreads();

    const int nk = K / 16;
    for (int kc = 0; kc < nk; kc++) {
        const int cur = kc & 1;
        if (kc + 1 < nk) {
            const float* Ap = Ag + (kc + 1) * 16;
            const float* Bp = Bg + (kc + 1) * 16;
#pragma unroll
            for (int l = 0; l < NLA; l++) {
                pa[l][0] = *(const float4*)(Ap + (size_t)l * RPP * K);
                pa[l][1] = *(const float4*)(Ap + (size_t)l * RPP * K + 4);
            }
#pragma unroll
            for (int l = 0; l < NLB; l++) {
                pb[l][0] = *(const float4*)(Bp + (size_t)l * RPP * K);
                pb[l][1] = *(const float4*)(Bp + (size_t)l * RPP * K + 4);
            }
        }

#pragma unroll
        for (int kk = 0; kk < 2; kk++) {
            const int kq = kk * 8 + (lane & 3);
            uint32_t af[MT][4], bf[NTT][2];
#pragma unroll
            for (int mt = 0; mt < MT; mt++) {
                int row = wm * WTM + mt * 16 + (lane >> 2);
                af[mt][0] = As[cur][row][kq];
                af[mt][1] = As[cur][row + 8][kq];
                af[mt][2] = As[cur][row][kq + 4];
                af[mt][3] = As[cur][row + 8][kq + 4];
            }
#pragma unroll
            for (int nt = 0; nt < NTT; nt++) {
                int nr = wn * WTN + nt * 8 + (lane >> 2);
                bf[nt][0] = Bs[cur][nr][kq];
                bf[nt][1] = Bs[cur][nr][kq + 4];
            }
#pragma unroll
            for (int mt = 0; mt < MT; mt++)
#pragma unroll
                for (int nt = 0; nt < NTT; nt++)
                    mma_tf32(acc[mt][nt][0], acc[mt][nt][1],
                             acc[mt][nt][2], acc[mt][nt][3],
                             af[mt][0], af[mt][1], af[mt][2], af[mt][3],
                             bf[nt][0], bf[nt][1]);
        }

        if (kc + 1 < nk) store_tiles(cur ^ 1);
        __syncthreads();
    }

    float spsum = 0.f;
#pragma unroll
    for (int mt = 0; mt < MT; mt++) {
        int row = bm + wm * WTM + mt * 16 + (lane >> 2);
#pragma unroll
        for (int nt = 0; nt < NTT; nt++) {
            int col = bn + wn * WTN + nt * 8 + (lane & 3) * 2;
            float* a4 = acc[mt][nt];
            size_t i0 = (size_t)row * N + col;
            size_t i1 = (size_t)(row + 8) * N + col;
            float2 r0 = make_float2(a4[0], a4[1]);
            float2 r1 = make_float2(a4[2], a4[3]);
            if (EPI == 4) {
                spsum += softplusf(r0.x) + softplusf(r0.y) +
                         softplusf(r1.x) + softplusf(r1.y);
            }
            *(float2*)(C + i0) = r0;
            *(float2*)(C + i1) = r1;
        }
    }
    if (EPI == 4) {
        sred[tid] = spsum; __syncthreads();
        for (int st = THREADS / 2; st > 0; st >>= 1) {
            if (tid < st) sred[tid] += sred[tid + st];
            __syncthreads();
        }
        if (tid == 0) atomicAdd(&g_acc[0], (double)sred[0]);
    }
}

template<int BM, int BN, int WM, int WN, int EPI>
__global__ __launch_bounds__(WM * WN * 32)
void gemm_tc(const float* __restrict__ A, const float* __restrict__ Bw,
             float* __restrict__ C, const float* __restrict__ G, int N, int K) {
    gemm_tc_core<BM, BN, WM, WN, EPI>(A, Bw, C, G, N, K,
                                      blockIdx.x * BM, blockIdx.y * BN);
}

// =======================================================================
//  Split-bf16 (hi+lo) NT-GEMM:  C[m,n] (op)= sum_k A[m,k]*W[n,k]
//  Accuracy ~1.5e-5 rel (drops only lo*lo).  3x m16n8k16 bf16 mma per k16.
//  smem row: 16 u32 per k16 chunk = 8 hi-pairs | 8 lo-pairs, stride TLD=20.
//  EPI: 0=store 1=add(residual) 2=silu 3=mulG
// =======================================================================
template<int BM, int BN, int WM, int WN, int EPI>
__device__ __forceinline__ void gemm_bf_core(const float* __restrict__ A,
                                             const float* __restrict__ Bw,
                                             float* __restrict__ C,
                                             const float* __restrict__ G,
                                             int N, int K,
                                             int bm, int bn) {
    constexpr int THREADS = WM * WN * 32;
    constexpr int WTM = BM / WM;
    constexpr int WTN = BN / WN;
    constexpr int MT  = WTM / 16;
    constexpr int NTT = WTN / 8;
    constexpr int RPP = THREADS / 2;
    constexpr int NLA = BM / RPP;
    constexpr int NLB = BN / RPP;

    __shared__ uint32_t As[2][BM][TLD];
    __shared__ uint32_t Bs[2][BN][TLD];

    const int tid  = threadIdx.x;
    const int lane = tid & 31;
    const int wid  = tid >> 5;
    const int wm   = wid / WN;
    const int wn   = wid % WN;

    const int lr = tid >> 1;
    const int ks = (tid & 1) * 8;   // float offset in k16 chunk: 0 or 8
    const int js = ks >> 1;         // pair index: 0 or 4
    const float* Ag = A  + (size_t)(bm + lr) * K + ks;
    const float* Bg = Bw + (size_t)(bn + lr) * K + ks;

    float acc[MT][NTT][4];
#pragma unroll
    for (int i = 0; i < MT; i++)
#pragma unroll
        for (int j = 0; j < NTT; j++)
#pragma unroll
            for (int q = 0; q < 4; q++) acc[i][j][q] = 0.f;

    float4 pa[NLA][2], pb[NLB][2];

#pragma unroll
    for (int l = 0; l < NLA; l++) {
        pa[l][0] = *(const float4*)(Ag + (size_t)l * RPP * K);
        pa[l][1] = *(const float4*)(Ag + (size_t)l * RPP * K + 4);
    }
#pragma unroll
    for (int l = 0; l < NLB; l++) {
        pb[l][0] = *(const float4*)(Bg + (size_t)l * RPP * K);
        pb[l][1] = *(const float4*)(Bg + (size_t)l * RPP * K + 4);
    }

    auto cvt_store = [&](uint32_t (*S)[TLD], int row, float4 v0, float4 v1) {
        uint4 hu = make_uint4(pkbf2(v0.x, v0.y), pkbf2(v0.z, v0.w),
                              pkbf2(v1.x, v1.y), pkbf2(v1.z, v1.w));
        uint4 lu = make_uint4(pkbf2(v0.x - bfhi(v0.x), v0.y - bfhi(v0.y)),
                              pkbf2(v0.z - bfhi(v0.z), v0.w - bfhi(v0.w)),
                              pkbf2(v1.x - bfhi(v1.x), v1.y - bfhi(v1.y)),
                              pkbf2(v1.z - bfhi(v1.z), v1.w - bfhi(v1.w)));
        *(uint4*)&S[row][js]     = hu;
        *(uint4*)&S[row][8 + js] = lu;
    };

    auto store_tiles = [&](int buf) {
#pragma unroll
        for (int l = 0; l < NLA; l++) cvt_store(As[buf], lr + l * RPP, pa[l][0], pa[l][1]);
#pragma unroll
        for (int l = 0; l < NLB; l++) cvt_store(Bs[buf], lr + l * RPP, pb[l][0], pb[l][1]);
    };

    store_tiles(0);
    __syncthreads();

    const int nk = K / 16;
    for (int kc = 0; kc < nk; kc++) {
        const int cur = kc & 1;
        if (kc + 1 < nk) {
            const float* Ap = Ag + (kc + 1) * 16;
            const float* Bp = Bg + (kc + 1) * 16;
#pragma unroll
            for (int l = 0; l < NLA; l++) {
                pa[l][0] = *(const float4*)(Ap + (size_t)l * RPP * K);
                pa[l][1] = *(const float4*)(Ap + (size_t)l * RPP * K + 4);
            }
#pragma unroll
            for (int l = 0; l < NLB; l++) {
                pb[l][0] = *(const float4*)(Bp + (size_t)l * RPP * K);
                pb[l][1] = *(const float4*)(Bp + (size_t)l * RPP * K + 4);
            }
        }

        {
            const int jq = lane & 3;
            uint32_t ah[MT][4], al[MT][4], bh[NTT][2], bl[NTT][2];
#pragma unroll
            for (int mt = 0; mt < MT; mt++) {
                int row = wm * WTM + mt * 16 + (lane >> 2);
                ah[mt][0] = As[cur][row][jq];
                ah[mt][1] = As[cur][row + 8][jq];
                ah[mt][2] = As[cur][row][jq + 4];
                ah[mt][3] = As[cur][row + 8][jq + 4];
                al[mt][0] = As[cur][row][jq + 8];
                al[mt][1] = As[cur][row + 8][jq + 8];
                al[mt][2] = As[cur][row][jq + 12];
                al[mt][3] = As[cur][row + 8][jq + 12];
            }
#pragma unroll
            for (int nt = 0; nt < NTT; nt++) {
                int nr = wn * WTN + nt * 8 + (lane >> 2);
                bh[nt][0] = Bs[cur][nr][jq];
                bh[nt][1] = Bs[cur][nr][jq + 4];
                bl[nt][0] = Bs[cur][nr][jq + 8];
                bl[nt][1] = Bs[cur][nr][jq + 12];
            }
#pragma unroll
            for (int mt = 0; mt < MT; mt++)
#pragma unroll
                for (int nt = 0; nt < NTT; nt++) {
                    mma_bf16(acc[mt][nt][0], acc[mt][nt][1], acc[mt][nt][2], acc[mt][nt][3],
                             ah[mt][0], ah[mt][1], ah[mt][2], ah[mt][3],
                             bh[nt][0], bh[nt][1]);
                    mma_bf16(acc[mt][nt][0], acc[mt][nt][1], acc[mt][nt][2], acc[mt][nt][3],
                             ah[mt][0], ah[mt][1], ah[mt][2], ah[mt][3],
                             bl[nt][0], bl[nt][1]);
                    mma_bf16(acc[mt][nt][0], acc[mt][nt][1], acc[mt][nt][2], acc[mt][nt][3],
                             al[mt][0], al[mt][1], al[mt][2], al[mt][3],
                             bh[nt][0], bh[nt][1]);
                }
        }

        if (kc + 1 < nk) store_tiles(cur ^ 1);
        __syncthreads();
    }

    // ---------------- epilogue ----------------
#pragma unroll
    for (int mt = 0; mt < MT; mt++) {
        int row = bm + wm * WTM + mt * 16 + (lane >> 2);
#pragma unroll
        for (int nt = 0; nt < NTT; nt++) {
            int col = bn + wn * WTN + nt * 8 + (lane & 3) * 2;
            float* a4 = acc[mt][nt];
            size_t i0 = (size_t)row * N + col;
            size_t i1 = (size_t)(row + 8) * N + col;
            float2 r0 = make_float2(a4[0], a4[1]);
            float2 r1 = make_float2(a4[2], a4[3]);
            if (EPI == 1) {
                float2 o0 = *(const float2*)(C + i0);
                float2 o1 = *(const float2*)(C + i1);
                r0.x += o0.x; r0.y += o0.y;
                r1.x += o1.x; r1.y += o1.y;
            } else if (EPI == 2) {
                r0.x = r0.x / (1.f + expf(-r0.x));
                r0.y = r0.y / (1.f + expf(-r0.y));
                r1.x = r1.x / (1.f + expf(-r1.x));
                r1.y = r1.y / (1.f + expf(-r1.y));
            } else if (EPI == 3) {
                float2 g0 = *(const float2*)(G + i0);
                float2 g1v = *(const float2*)(G + i1);
                r0.x *= g0.x; r0.y *= g0.y;
                r1.x *= g1v.x; r1.y *= g1v.y;
            }
            *(float2*)(C + i0) = r0;
            *(float2*)(C + i1) = r1;
        }
    }
}

template<int BM, int BN, int WM, int WN, int EPI>
__global__ __launch_bounds__(WM * WN * 32)
void gemm_bf(const float* __restrict__ A, const float* __restrict__ Bw,
             float* __restrict__ C, const float* __restrict__ G, int N, int K) {
    gemm_bf_core<BM, BN, WM, WN, EPI>(A, Bw, C, G, N, K,
                                      blockIdx.x * BM, blockIdx.y * BN);
}

__global__ __launch_bounds__(128)
void gemm_qkv_bf(const float* __restrict__ A,
                 const float* __restrict__ B0, const float* __restrict__ B1,
                 const float* __restrict__ B2,
                 float* __restrict__ C0, float* __restrict__ C1, float* __restrict__ C2,
                 int N, int K) {
    const float* Bz = (blockIdx.z == 0) ? B0 : (blockIdx.z == 1) ? B1 : B2;
    float*       Cz = (blockIdx.z == 0) ? C0 : (blockIdx.z == 1) ? C1 : C2;
    gemm_bf_core<64, 64, 2, 2, 0>(A, Bz, Cz, nullptr, N, K,
                                  blockIdx.x * 64, blockIdx.y * 64);
}

// ---------------- RoPE ----------------
__global__ void rope_table_kernel() {
    int i = blockIdx.x * blockDim.x + threadIdx.x;
    if (i >= S_ * 32) return;
    int s = i / 32, p = i - (i / 32) * 32;
    float f   = expf((float)(2 * p) * (-logf(10000.0f) / (float)HD_));
    float ang = (float)s * f;
    double a  = (double)ang;
    g_rope[i] = make_float2((float)cos(a), (float)sin(a));
}

__global__ void rope_apply_kernel() {
    int idx = blockIdx.x * blockDim.x + threadIdx.x;          // over B*S*H*32
    if (idx >= B_ * S_ * H_ * 32) return;
    int p = idx & 31;
    int h = (idx >> 5) % H_;
    int s = (idx / (32 * H_)) % S_;
    int b = idx / (32 * H_ * S_);
    float2 cs = g_rope[s * 32 + p];
    int base = ((b * S_ + s) * D_) + h * HD_ + 2 * p;
    float xr, xi;
    xr = g_q[base]; xi = g_q[base + 1];
    g_q[base]     = xr * cs.x - xi * cs.y;
    g_q[base + 1] = xr * cs.y + xi * cs.x;
    xr = g_k[base]; xi = g_k[base + 1];
    g_k[base]     = xr * cs.x - xi * cs.y;
    g_k[base + 1] = xr * cs.y + xi * cs.x;
}

// ---------------- flash-style attention ----------------
// block = (q-tile of 64, b*h).  K/V tiles in smem, online softmax.
// thread t: local q row = t>>2, d-slice = (t&3)*16 .. +15
__global__ __launch_bounds__(256)
void attn_flash() {
    const int qt = blockIdx.x;
    const int bh = blockIdx.y;
    const int b = bh / H_, h = bh - (bh / H_) * H_;
    const int tid = threadIdx.x;
    const int q  = tid >> 2;
    const int dg = (tid & 3) * 16;
    const int q0 = qt * 64;

    __shared__ float KS[64][68];   // K tile, then reused for scores/probs
    __shared__ float Vs[64][68];
    __shared__ float rowm[64], rows[64], cfs[64];

    // preload this thread's q row (64 floats)
    float4 qr[16];
    const float* qp = g_q + ((size_t)(b * S_ + q0 + q)) * D_ + h * HD_;
#pragma unroll
    for (int j = 0; j < 16; j++) qr[j] = *(const float4*)(qp + 4 * j);

    float acc[16];
#pragma unroll
    for (int j = 0; j < 16; j++) acc[j] = 0.f;
    if (tid < 64) { rowm[tid] = -1e30f; rows[tid] = 0.f; }

    for (int k0 = 0; k0 <= q0; k0 += 64) {
        // load K,V tiles
        {
            int r = tid >> 2, c = (tid & 3) * 16;
            const float* kp = g_k + ((size_t)(b * S_ + k0 + r)) * D_ + h * HD_ + c;
            const float* vp = g_v + ((size_t)(b * S_ + k0 + r)) * D_ + h * HD_ + c;
#pragma unroll
            for (int j = 0; j < 4; j++) {
                *(float4*)&KS[r][c + 4 * j] = *(const float4*)(kp + 4 * j);
                *(float4*)&Vs[r][c + 4 * j] = *(const float4*)(vp + 4 * j);
            }
        }
        __syncthreads();

        // scores to registers (16 per thread: k = (tid&3)*16 + j)
        float sreg[16];
        {
            const int kb = (tid & 3) * 16;
#pragma unroll
            for (int j = 0; j < 16; j++) {
                int kk = kb + j;
                float d = 0.f;
#pragma unroll
                for (int t4 = 0; t4 < 16; t4++) {
                    float4 kv = *(const float4*)&KS[kk][4 * t4];
                    d += qr[t4].x * kv.x + qr[t4].y * kv.y +
                         qr[t4].z * kv.z + qr[t4].w * kv.w;
                }
                sreg[j] = (k0 + kk <= q0 + q) ? d * 0.125f : -1e30f;
            }
        }
        __syncthreads();   // everyone done reading K tile

        // write scores into KS (reuse as score buffer)
        {
            const int kb = (tid & 3) * 16;
#pragma unroll
            for (int j = 0; j < 16; j++) KS[q][kb + j] = sreg[j];
        }
        __syncthreads();

        // online softmax per q row
        if (tid < 64) {
            float mo = rowm[tid];
            float tm = mo;
#pragma unroll 8
            for (int kk = 0; kk < 64; kk++) tm = fmaxf(tm, KS[tid][kk]);
            float cf = expf(mo - tm);
            float ps = 0.f;
#pragma unroll 8
            for (int kk = 0; kk < 64; kk++) {
                float p = expf(KS[tid][kk] - tm);
                KS[tid][kk] = p;
                ps += p;
            }
            rowm[tid] = tm;
            rows[tid] = rows[tid] * cf + ps;
            cfs[tid] = cf;
        }
        __syncthreads();

        // accumulate P @ V
        {
            float cf = cfs[q];
#pragma unroll
            for (int j = 0; j < 16; j++) acc[j] *= cf;
            for (int kk = 0; kk < 64; kk++) {
                float p = KS[q][kk];
#pragma unroll
                for (int j4 = 0; j4 < 4; j4++) {
                    float4 vv = *(const float4*)&Vs[kk][dg + 4 * j4];
                    acc[4 * j4 + 0] += p * vv.x;
                    acc[4 * j4 + 1] += p * vv.y;
                    acc[4 * j4 + 2] += p * vv.z;
                    acc[4 * j4 + 3] += p * vv.w;
                }
            }
        }
        __syncthreads();   // before next tile overwrites KS/Vs
    }

    float inv = 1.f / rows[q];
    float* op = g_o + ((size_t)(b * S_ + q0 + q)) * D_ + h * HD_ + dg;
#pragma unroll
    for (int j4 = 0; j4 < 4; j4++) {
        float4 r = make_float4(acc[4 * j4] * inv, acc[4 * j4 + 1] * inv,
                               acc[4 * j4 + 2] * inv, acc[4 * j4 + 3] * inv);
        *(float4*)(op + 4 * j4) = r;
    }
}

// ---------------- sparse BCE correction ----------------
__global__ void corr_kernel(const int* __restrict__ y) {
    int s = blockIdx.x * blockDim.x + threadIdx.x;
    if (s >= S_) return;
    int tok[2][FCS_];
    for (int b = 0; b < 2; b++)
        for (int j = 0; j < FCS_; j++)
            tok[b][j] = y[b * YW_ + (FCS_ - 1) + ((s - (FCS_ - 1) + j + S_) & (S_ - 1))];
    double dsum = 0.0;
    for (int b = 0; b < 2; b++)
        for (int j = 0; j < FCS_; j++) {
            int v = tok[b][j];
            bool first = true;
            for (int b2 = 0; b2 <= b && first; b2++) {
                int jmax = (b2 == b) ? j : FCS_;
                for (int j2 = 0; j2 < jmax; j2++)
                    if (tok[b2][j2] == v) { first = false; break; }
            }
            if (!first) continue;
            int c0 = 0, c1 = 0;
            for (int j2 = 0; j2 < FCS_; j2++) {
                c0 += (tok[0][j2] == v);
                c1 += (tok[1][j2] == v);
            }
            float w = (c0 > 1 || c1 > 1) ? 1.5f : 1.0f;
            for (int b2 = 0; b2 < 2; b2++) {
                float cv = g_c[((size_t)(b2 * S_ + s)) * V_ + v];
                float t  = ((b2 == 0 ? c0 : c1) > 0) ? 1.f : 0.f;
                dsum += (double)((w - 1.f) * softplusf(cv) - w * t * cv);
            }
        }
    atomicAdd(&g_acc[1], dsum);
}

// ---------------- logits += exp-kernel context (ring-buffer window) ----
// context[s] = sum_{d=1..8} e^(8-d) * c[s-d],  e = exp(-conv_w[0])
#define CTX_CHUNK 128
__global__ void ctx_scan_kernel(float* __restrict__ logits, const float* __restrict__ conv_w) {
    int v = blockIdx.x * blockDim.x + threadIdx.x;
    if (v >= V_) return;
    int b  = blockIdx.y;
    int s0 = blockIdx.z * CTX_CHUNK;     // multiple of 8
    float e = expf(-conv_w[0]);

    float pw[FCS_];
    pw[FCS_ - 1] = 1.f;
#pragma unroll
    for (int d = FCS_ - 1; d >= 1; --d) pw[d - 1] = pw[d] * e;

    float ring[FCS_];
#pragma unroll
    for (int j = 1; j <= FCS_; j++) {
        int sp = s0 - j;
        ring[(8 - j) & 7] = (sp >= 0) ? g_c[((size_t)(b * S_ + sp)) * V_ + v] : 0.f;
    }

    for (int t = 0; t < CTX_CHUNK / 8; t++) {
#pragma unroll
        for (int u = 0; u < 8; u++) {
            int s = s0 + 8 * t + u;
            size_t idx = ((size_t)(b * S_ + s)) * V_ + v;
            float ctx = 0.f;
#pragma unroll
            for (int d = 1; d <= FCS_; d++)
                ctx += pw[d - 1] * ring[(u - d) & 7];
            logits[idx] += ctx;
            ring[u] = g_c[idx];
        }
    }
}

// ---------------- NLL ----------------
__global__ void nll_kernel(const float* __restrict__ logits, const int* __restrict__ y) {
    int row = blockIdx.x;
    int b = row / S_, s = row - (row / S_) * S_;
    const float* lp = logits + (size_t)row * V_;
    __shared__ float red[256];
    float m = -1e30f;
    for (int v = threadIdx.x; v < V_; v += 256) m = fmaxf(m, lp[v]);
    red[threadIdx.x] = m; __syncthreads();
    for (int st = 128; st > 0; st >>= 1) {
        if (threadIdx.x < st) red[threadIdx.x] = fmaxf(red[threadIdx.x], red[threadIdx.x + st]);
        __syncthreads();
    }
    m = red[0];
    __syncthreads();
    float ssum = 0.f;
    for (int v = threadIdx.x; v < V_; v += 256) ssum += expf(lp[v] - m);
    red[threadIdx.x] = ssum; __syncthreads();
    for (int st = 128; st > 0; st >>= 1) {
        if (threadIdx.x < st) red[threadIdx.x] += red[threadIdx.x + st];
        __syncthreads();
    }
    if (threadIdx.x == 0) {
        int yt = y[b * YW_ + s];
        if (yt != -1) {
            float lse = m + logf(red[0]);
            atomicAdd(&g_acc[2], (double)(lse - lp[yt]));
            atomicAdd(&g_acc[3], 1.0);
        }
    }
}

__global__ void finalize_kernel(float* __restrict__ out) {
    double cnt = g_acc[3] < 1.0 ? 1.0 : g_acc[3];
    out[(size_t)NT_ * V_]     = (float)(g_acc[2] / cnt);
    out[(size_t)NT_ * V_ + 1] = (float)((g_acc[0] + g_acc[1]) / ((double)NT_ * (double)V_));
}

// ---------------- launcher ----------------
extern "C" void kernel_launch(void* const* d_in, const int* in_sizes, int n_in,
                              void* d_out, int out_size) {
    const int*   x      = (const int*)  d_in[0];
    const int*   y      = (const int*)  d_in[1];
    const float* emb    = (const float*)d_in[2];
    const float* wq     = (const float*)d_in[3];
    const float* wk     = (const float*)d_in[4];
    const float* wv     = (const float*)d_in[5];
    const float* wo     = (const float*)d_in[6];
    const float* w1     = (const float*)d_in[7];
    const float* w2     = (const float*)d_in[8];
    const float* w3     = (const float*)d_in[9];
    const float* attn_n = (const float*)d_in[10];
    const float* ffn_n  = (const float*)d_in[11];
    const float* out_n  = (const float*)d_in[12];
    const float* w_out  = (const float*)d_in[13];
    const float* w_ctx  = (const float*)d_in[14];
    const float* conv_w = (const float*)d_in[15];
    float* out = (float*)d_out;

    float *h_, *a_, *q_, *k_, *v_, *o_, *g1_, *u1_, *c_;
    cudaGetSymbolAddress((void**)&h_,  g_h);
    cudaGetSymbolAddress((void**)&a_,  g_a);
    cudaGetSymbolAddress((void**)&q_,  g_q);
    cudaGetSymbolAddress((void**)&k_,  g_k);
    cudaGetSymbolAddress((void**)&v_,  g_v);
    cudaGetSymbolAddress((void**)&o_,  g_o);
    cudaGetSymbolAddress((void**)&g1_, g_g1);
    cudaGetSymbolAddress((void**)&u1_, g_u1);
    cudaGetSymbolAddress((void**)&c_,  g_c);

    zero_acc_kernel<<<1, 32>>>();
    embed_kernel<<<(NT_ * D_ + 255) / 256, 256>>>(x, emb);
    rope_table_kernel<<<(S_ * 32 + 255) / 256, 256>>>();

    dim3 gQKV(NT_ / 64, D_ / 64, 3);     // 16 x 12 x 3 (64x64 tiles)
    dim3 gDs (NT_ / 64, D_ / 64);        // 16 x 12
    dim3 gF  (NT_ / 128, F_ / 64);       // 8 x 32 (128x64 tiles)
    dim3 gTF (NT_ / 128, V_ / 128);      // 8 x 250 (m fast for L2 weight reuse)

    for (int i = 0; i < L_; i++) {
        const float* wq_i = wq + (size_t)i * D_ * D_;
        const float* wk_i = wk + (size_t)i * D_ * D_;
        const float* wv_i = wv + (size_t)i * D_ * D_;
        const float* wo_i = wo + (size_t)i * D_ * D_;
        const float* w1_i = w1 + (size_t)i * F_ * D_;
        const float* w2_i = w2 + (size_t)i * D_ * F_;
        const float* w3_i = w3 + (size_t)i * F_ * D_;

        rmsnorm_kernel<<<NT_, 256>>>(h_, attn_n + i * D_, a_);
        gemm_qkv_bf<<<gQKV, 128>>>(a_, wq_i, wk_i, wv_i, q_, k_, v_, D_, D_);
        rope_apply_kernel<<<(B_ * S_ * H_ * 32 + 255) / 256, 256>>>();
        attn_flash<<<dim3(S_ / 64, B_ * H_), 256>>>();
        gemm_bf<64, 64, 2, 2, 1><<<gDs, 128>>>(o_, wo_i, h_, nullptr, D_, D_);

        rmsnorm_kernel<<<NT_, 256>>>(h_, ffn_n + i * D_, a_);
        gemm_bf<128, 64, 2, 2, 2><<<gF, 128>>>(a_, w1_i, g1_, nullptr, F_, D_);
        gemm_bf<128, 64, 2, 2, 3><<<gF, 128>>>(a_, w3_i, u1_, g1_, F_, D_);
        gemm_bf<64, 64, 2, 2, 1><<<gDs, 128>>>(u1_, w2_i, h_, nullptr, D_, F_);
    }

    rmsnorm_kernel<<<NT_, 256>>>(h_, out_n, a_);
    gemm_tc<128, 128, 2, 4, 0><<<gTF, 256>>>(a_, w_out, out, nullptr, V_, D_);  // logits
    gemm_tc<128, 128, 2, 4, 4><<<gTF, 256>>>(a_, w_ctx, c_,  nullptr, V_, D_);  // c + softplus

    corr_kernel<<<(S_ + 255) / 256, 256>>>(y);
    ctx_scan_kernel<<<dim3((V_ + 255) / 256, B_, S_ / CTX_CHUNK), 256>>>(out, conv_w);
    nll_kernel<<<NT_, 256>>>(out, y);
    finalize_kernel<<<1, 1>>>(out);
}